// round 1
// baseline (speedup 1.0000x reference)
#include <cuda_runtime.h>
#include <math.h>

#define S_TOK 8192
#define DM    1024
#define FFDIM 4096
#define NE    8
#define CAP   1280

#define BM 128
#define BN 128
#define BK 16
#define ASTR 20    // BK + 4  (conflict-free for A-fragment loads)
#define BSTR 136   // BN + 8  (conflict-free for B-fragment loads)

// ---------------- scratch (device globals; no allocation allowed) ----------------
__device__ int   g_topk_i[S_TOK * 2];
__device__ float g_topk_w[S_TOK * 2];
__device__ int   g_slot[S_TOK * 2];
__device__ int   g_idx[NE * CAP];
__device__ int   g_cnt[NE];
__device__ float g_h[(size_t)NE * CAP * FFDIM];     // expert hidden activations
__device__ float g_oute[(size_t)NE * CAP * DM];     // expert outputs (pre-combine)

__device__ __forceinline__ float to_tf32(float x) {
    unsigned u;
    asm("cvt.rna.tf32.f32 %0, %1;" : "=r"(u) : "f"(x));
    return __uint_as_float(u);
}

__device__ __forceinline__ void mma_tf32(float* d, const unsigned* a, const unsigned* b) {
    asm volatile(
        "mma.sync.aligned.m16n8k8.row.col.f32.tf32.tf32.f32 "
        "{%0,%1,%2,%3}, {%4,%5,%6,%7}, {%8,%9}, {%0,%1,%2,%3};\n"
        : "+f"(d[0]), "+f"(d[1]), "+f"(d[2]), "+f"(d[3])
        : "r"(a[0]), "r"(a[1]), "r"(a[2]), "r"(a[3]), "r"(b[0]), "r"(b[1]));
}

// ---------------- gating: logits -> top2 -> normalized weights ----------------
__global__ __launch_bounds__(256) void gate_kernel(const float* __restrict__ x,
                                                   const float* __restrict__ gw,
                                                   const float* __restrict__ gb) {
    __shared__ float sgw[DM * 9];  // padded row stride 9 -> conflict-free
    int tid = threadIdx.x;
    for (int i = tid; i < DM * NE; i += 256) sgw[(i >> 3) * 9 + (i & 7)] = gw[i];
    __syncthreads();

    int warp = tid >> 5, lane = tid & 31;
    int t = blockIdx.x * 8 + warp;
    const float* xr = x + (size_t)t * DM;
    float acc[NE];
#pragma unroll
    for (int e = 0; e < NE; e++) acc[e] = 0.f;
    for (int d = lane; d < DM; d += 32) {
        float xv = xr[d];
        const float* g = &sgw[d * 9];
#pragma unroll
        for (int e = 0; e < NE; e++) acc[e] += xv * g[e];
    }
#pragma unroll
    for (int e = 0; e < NE; e++) {
#pragma unroll
        for (int off = 16; off; off >>= 1)
            acc[e] += __shfl_xor_sync(0xffffffffu, acc[e], off);
    }
    if (lane == 0) {
        float l[NE];
#pragma unroll
        for (int e = 0; e < NE; e++) l[e] = acc[e] + gb[e];
        int i0 = 0;
#pragma unroll
        for (int e = 1; e < NE; e++) if (l[e] > l[i0]) i0 = e;   // strict > : lowest index wins (jax tie-break)
        int i1 = (i0 == 0) ? 1 : 0;
#pragma unroll
        for (int e = 0; e < NE; e++) if (e != i0 && l[e] > l[i1]) i1 = e;
        // normalized top-2 weights: p0/(p0+p1) = 1/(1+exp(l1-l0))
        float p1 = expf(l[i1] - l[i0]);
        float w0 = 1.f / (1.f + p1);
        g_topk_i[2 * t] = i0; g_topk_i[2 * t + 1] = i1;
        g_topk_w[2 * t] = w0; g_topk_w[2 * t + 1] = 1.f - w0;
    }
}

// ---------------- routing: order-preserving capacity assignment ----------------
__global__ __launch_bounds__(256) void route_kernel() {
    __shared__ int wsum[8];
    __shared__ int run[NE];
    int tid = threadIdx.x, lane = tid & 31, warp = tid >> 5;
    if (tid < NE) run[tid] = 0;
    __syncthreads();

    for (int base = 0; base < S_TOK; base += 256) {
        int t = base + tid;
        int i0 = g_topk_i[2 * t], i1 = g_topk_i[2 * t + 1];
        int rank0 = 0, rank1 = 0;
        for (int e = 0; e < NE; e++) {
            int v = (i0 == e || i1 == e) ? 1 : 0;
#pragma unroll
            for (int off = 1; off < 32; off <<= 1) {
                int u = __shfl_up_sync(0xffffffffu, v, off);
                if (lane >= off) v += u;
            }
            if (lane == 31) wsum[warp] = v;
            __syncthreads();
            int woff = 0, total = 0;
#pragma unroll
            for (int w = 0; w < 8; w++) { int s = wsum[w]; total += s; if (w < warp) woff += s; }
            int rank = run[e] + woff + v;   // inclusive cumsum, global token order
            if (i0 == e) rank0 = rank;
            if (i1 == e) rank1 = rank;
            __syncthreads();                // all reads of wsum/run done
            if (tid == 0) run[e] += total;
        }
        int s0 = (rank0 <= CAP) ? rank0 - 1 : -1;
        int s1 = (rank1 <= CAP) ? rank1 - 1 : -1;
        g_slot[2 * t] = s0; g_slot[2 * t + 1] = s1;
        if (s0 >= 0) g_idx[i0 * CAP + s0] = t;
        if (s1 >= 0) g_idx[i1 * CAP + s1] = t;
    }
    __syncthreads();
    if (tid < NE) g_cnt[tid] = min(run[tid], CAP);
}

// ---------------- expert GEMM (tf32 mma.sync, fp32 accumulate) ----------------
// GATHER=true : A rows gathered from x via g_idx (invalid rows -> zeros), epilogue relu(.+b1) -> g_h
// GATHER=false: A = g_h rows, epilogue .+b2 -> g_oute
template<bool GATHER, bool RELU, int KDIM, int NDIM>
__global__ __launch_bounds__(256, 2)
void gemm_kernel(const float* __restrict__ Aglob,
                 const float* __restrict__ Wglob,
                 const float* __restrict__ biasGlob) {
    __shared__ float As[BM][ASTR];
    __shared__ float Bs[BK][BSTR];
    __shared__ int sTok[BM];

    const int e = blockIdx.z;
    const int rowBase = blockIdx.y * BM;
    const int nBase = blockIdx.x * BN;
    const int tid = threadIdx.x;

    const float* Abase = GATHER ? Aglob : (g_h + (size_t)e * CAP * KDIM);
    const float* W = Wglob + (size_t)e * KDIM * NDIM;
    const float* bias = biasGlob + e * NDIM;
    float* Out = (RELU ? g_h : g_oute) + (size_t)e * CAP * NDIM;

    if (tid < BM) {
        int r = rowBase + tid;
        sTok[tid] = GATHER ? ((r < g_cnt[e]) ? g_idx[e * CAP + r] : -1) : r;
    }
    __syncthreads();

    float acc[4][4][4];
#pragma unroll
    for (int mt = 0; mt < 4; mt++)
#pragma unroll
        for (int nt = 0; nt < 4; nt++)
#pragma unroll
            for (int i = 0; i < 4; i++) acc[mt][nt][i] = 0.f;

    const int warp = tid >> 5, lane = tid & 31;
    const int wm = warp >> 2, wn = warp & 3;       // 2x4 warp grid; warp tile 64x32
    const int gid = lane >> 2, tig = lane & 3;

    const int aRow = tid >> 2;          // 0..63
    const int aCol = (tid & 3) * 4;
    const int bRow = tid >> 5;          // 0..7
    const int bCol = (tid & 31) * 4;

    for (int kk = 0; kk < KDIM; kk += BK) {
#pragma unroll
        for (int rr = 0; rr < BM; rr += 64) {
            int tok = sTok[aRow + rr];
            float4 v = make_float4(0.f, 0.f, 0.f, 0.f);
            if (tok >= 0)
                v = *reinterpret_cast<const float4*>(Abase + (size_t)tok * KDIM + kk + aCol);
            As[aRow + rr][aCol + 0] = to_tf32(v.x);
            As[aRow + rr][aCol + 1] = to_tf32(v.y);
            As[aRow + rr][aCol + 2] = to_tf32(v.z);
            As[aRow + rr][aCol + 3] = to_tf32(v.w);
        }
#pragma unroll
        for (int rr = 0; rr < BK; rr += 8) {
            float4 v = *reinterpret_cast<const float4*>(
                W + (size_t)(kk + bRow + rr) * NDIM + nBase + bCol);
            Bs[bRow + rr][bCol + 0] = to_tf32(v.x);
            Bs[bRow + rr][bCol + 1] = to_tf32(v.y);
            Bs[bRow + rr][bCol + 2] = to_tf32(v.z);
            Bs[bRow + rr][bCol + 3] = to_tf32(v.w);
        }
        __syncthreads();

#pragma unroll
        for (int kf = 0; kf < BK; kf += 8) {
            unsigned a[4][4], b[4][2];
#pragma unroll
            for (int mt = 0; mt < 4; mt++) {
                int r = wm * 64 + mt * 16 + gid;
                a[mt][0] = __float_as_uint(As[r][kf + tig]);
                a[mt][1] = __float_as_uint(As[r + 8][kf + tig]);
                a[mt][2] = __float_as_uint(As[r][kf + tig + 4]);
                a[mt][3] = __float_as_uint(As[r + 8][kf + tig + 4]);
            }
#pragma unroll
            for (int nt = 0; nt < 4; nt++) {
                int c = wn * 32 + nt * 8 + gid;
                b[nt][0] = __float_as_uint(Bs[kf + tig][c]);
                b[nt][1] = __float_as_uint(Bs[kf + tig + 4][c]);
            }
#pragma unroll
            for (int mt = 0; mt < 4; mt++)
#pragma unroll
                for (int nt = 0; nt < 4; nt++)
                    mma_tf32(acc[mt][nt], a[mt], b[nt]);
        }
        __syncthreads();
    }

    // epilogue: + bias (, relu), store
#pragma unroll
    for (int mt = 0; mt < 4; mt++) {
        int r0 = rowBase + wm * 64 + mt * 16 + gid;
#pragma unroll
        for (int nt = 0; nt < 4; nt++) {
            int c = nBase + wn * 32 + nt * 8 + 2 * tig;
            float bv0 = bias[c], bv1 = bias[c + 1];
            float v00 = acc[mt][nt][0] + bv0;
            float v01 = acc[mt][nt][1] + bv1;
            float v10 = acc[mt][nt][2] + bv0;
            float v11 = acc[mt][nt][3] + bv1;
            if (RELU) {
                v00 = fmaxf(v00, 0.f); v01 = fmaxf(v01, 0.f);
                v10 = fmaxf(v10, 0.f); v11 = fmaxf(v11, 0.f);
            }
            *reinterpret_cast<float2*>(Out + (size_t)r0 * NDIM + c) = make_float2(v00, v01);
            *reinterpret_cast<float2*>(Out + (size_t)(r0 + 8) * NDIM + c) = make_float2(v10, v11);
        }
    }
}

// ---------------- combine: per-token weighted sum of its expert rows ----------------
__global__ __launch_bounds__(256) void combine_kernel(float* __restrict__ out) {
    int t = blockIdx.x;
    int i0 = g_topk_i[2 * t], i1 = g_topk_i[2 * t + 1];
    int s0 = g_slot[2 * t], s1 = g_slot[2 * t + 1];
    float w0 = g_topk_w[2 * t], w1v = g_topk_w[2 * t + 1];
    int d = threadIdx.x * 4;
    float4 a = make_float4(0.f, 0.f, 0.f, 0.f);
    if (s0 >= 0) {
        float4 v = *reinterpret_cast<const float4*>(g_oute + ((size_t)i0 * CAP + s0) * DM + d);
        a.x += w0 * v.x; a.y += w0 * v.y; a.z += w0 * v.z; a.w += w0 * v.w;
    }
    if (s1 >= 0) {
        float4 v = *reinterpret_cast<const float4*>(g_oute + ((size_t)i1 * CAP + s1) * DM + d);
        a.x += w1v * v.x; a.y += w1v * v.y; a.z += w1v * v.z; a.w += w1v * v.w;
    }
    *reinterpret_cast<float4*>(out + (size_t)t * DM + d) = a;
}

// ---------------- launch ----------------
extern "C" void kernel_launch(void* const* d_in, const int* in_sizes, int n_in,
                              void* d_out, int out_size) {
    (void)in_sizes; (void)n_in; (void)out_size;
    const float* x      = (const float*)d_in[0];
    const float* gate_w = (const float*)d_in[1];
    const float* gate_b = (const float*)d_in[2];
    const float* w1     = (const float*)d_in[3];
    const float* b1     = (const float*)d_in[4];
    const float* w2     = (const float*)d_in[5];
    const float* b2     = (const float*)d_in[6];
    float* out = (float*)d_out;

    gate_kernel<<<S_TOK / 8, 256>>>(x, gate_w, gate_b);
    route_kernel<<<1, 256>>>();
    gemm_kernel<true,  true,  DM,    FFDIM><<<dim3(FFDIM / BN, CAP / BM, NE), 256>>>(x, w1, b1);
    gemm_kernel<false, false, FFDIM, DM   ><<<dim3(DM / BN,    CAP / BM, NE), 256>>>(x, w2, b2);
    combine_kernel<<<S_TOK, 256>>>(out);
}

// round 2
// speedup vs baseline: 1.6098x; 1.6098x over previous
#include <cuda_runtime.h>
#include <math.h>

#define S_TOK 8192
#define DM    1024
#define FFDIM 4096
#define NE    8
#define CAP   1280

#define BM 128
#define BN 128
#define BK 16
#define STAGES 4
#define ASTR 20    // BK + 4 floats (80B rows, 16B aligned, conflict-free frags)
#define BSTR 136   // BN + 8 floats (544B rows, 16B aligned, conflict-free frags)

#define A_STAGE_BYTES (BM * ASTR * 4)          // 10240
#define B_STAGE_BYTES (BK * BSTR * 4)          // 8704
#define STAGE_BYTES   (A_STAGE_BYTES + B_STAGE_BYTES)
#define SMEM_BYTES    (STAGES * STAGE_BYTES)   // 75776

// ---------------- scratch (device globals; no allocation allowed) ----------------
__device__ int   g_topk_i[S_TOK * 2];
__device__ float g_topk_w[S_TOK * 2];
__device__ int   g_slot[S_TOK * 2];
__device__ int   g_idx[NE * CAP];
__device__ int   g_cnt[NE];
__device__ float g_h[(size_t)NE * CAP * FFDIM];     // expert hidden activations
__device__ float g_oute[(size_t)NE * CAP * DM];     // expert outputs (pre-combine)

__device__ __forceinline__ float to_tf32(float x) {
    unsigned u;
    asm("cvt.rna.tf32.f32 %0, %1;" : "=r"(u) : "f"(x));
    return __uint_as_float(u);
}

__device__ __forceinline__ void mma_tf32(float* d, const unsigned* a, const unsigned* b) {
    asm volatile(
        "mma.sync.aligned.m16n8k8.row.col.f32.tf32.tf32.f32 "
        "{%0,%1,%2,%3}, {%4,%5,%6,%7}, {%8,%9}, {%0,%1,%2,%3};\n"
        : "+f"(d[0]), "+f"(d[1]), "+f"(d[2]), "+f"(d[3])
        : "r"(a[0]), "r"(a[1]), "r"(a[2]), "r"(a[3]), "r"(b[0]), "r"(b[1]));
}

__device__ __forceinline__ void cp_async16(unsigned smem_addr, const void* gptr, int src_bytes) {
    asm volatile("cp.async.ca.shared.global [%0], [%1], 16, %2;\n"
                 :: "r"(smem_addr), "l"(gptr), "r"(src_bytes));
}
__device__ __forceinline__ void cp_commit() {
    asm volatile("cp.async.commit_group;\n");
}
__device__ __forceinline__ void cp_wait2() {
    asm volatile("cp.async.wait_group 2;\n");
}

// ---------------- gating: logits -> top2 -> normalized weights ----------------
__global__ __launch_bounds__(256) void gate_kernel(const float* __restrict__ x,
                                                   const float* __restrict__ gw,
                                                   const float* __restrict__ gb) {
    __shared__ float sgw[DM * 9];
    int tid = threadIdx.x;
    for (int i = tid; i < DM * NE; i += 256) sgw[(i >> 3) * 9 + (i & 7)] = gw[i];
    __syncthreads();

    int warp = tid >> 5, lane = tid & 31;
    int t = blockIdx.x * 8 + warp;
    const float* xr = x + (size_t)t * DM;
    float acc[NE];
#pragma unroll
    for (int e = 0; e < NE; e++) acc[e] = 0.f;
    for (int d = lane; d < DM; d += 32) {
        float xv = xr[d];
        const float* g = &sgw[d * 9];
#pragma unroll
        for (int e = 0; e < NE; e++) acc[e] += xv * g[e];
    }
#pragma unroll
    for (int e = 0; e < NE; e++) {
#pragma unroll
        for (int off = 16; off; off >>= 1)
            acc[e] += __shfl_xor_sync(0xffffffffu, acc[e], off);
    }
    if (lane == 0) {
        float l[NE];
#pragma unroll
        for (int e = 0; e < NE; e++) l[e] = acc[e] + gb[e];
        int i0 = 0;
#pragma unroll
        for (int e = 1; e < NE; e++) if (l[e] > l[i0]) i0 = e;
        int i1 = (i0 == 0) ? 1 : 0;
#pragma unroll
        for (int e = 0; e < NE; e++) if (e != i0 && l[e] > l[i1]) i1 = e;
        float p1 = expf(l[i1] - l[i0]);
        float w0 = 1.f / (1.f + p1);
        g_topk_i[2 * t] = i0; g_topk_i[2 * t + 1] = i1;
        g_topk_w[2 * t] = w0; g_topk_w[2 * t + 1] = 1.f - w0;
    }
}

// ---------------- routing: order-preserving capacity assignment ----------------
__global__ __launch_bounds__(256) void route_kernel() {
    __shared__ int wsum[8];
    __shared__ int run[NE];
    int tid = threadIdx.x, lane = tid & 31, warp = tid >> 5;
    if (tid < NE) run[tid] = 0;
    __syncthreads();

    for (int base = 0; base < S_TOK; base += 256) {
        int t = base + tid;
        int i0 = g_topk_i[2 * t], i1 = g_topk_i[2 * t + 1];
        int rank0 = 0, rank1 = 0;
        for (int e = 0; e < NE; e++) {
            int v = (i0 == e || i1 == e) ? 1 : 0;
#pragma unroll
            for (int off = 1; off < 32; off <<= 1) {
                int u = __shfl_up_sync(0xffffffffu, v, off);
                if (lane >= off) v += u;
            }
            if (lane == 31) wsum[warp] = v;
            __syncthreads();
            int woff = 0, total = 0;
#pragma unroll
            for (int w = 0; w < 8; w++) { int s = wsum[w]; total += s; if (w < warp) woff += s; }
            int rank = run[e] + woff + v;
            if (i0 == e) rank0 = rank;
            if (i1 == e) rank1 = rank;
            __syncthreads();
            if (tid == 0) run[e] += total;
        }
        int s0 = (rank0 <= CAP) ? rank0 - 1 : -1;
        int s1 = (rank1 <= CAP) ? rank1 - 1 : -1;
        g_slot[2 * t] = s0; g_slot[2 * t + 1] = s1;
        if (s0 >= 0) g_idx[i0 * CAP + s0] = t;
        if (s1 >= 0) g_idx[i1 * CAP + s1] = t;
    }
    __syncthreads();
    if (tid < NE) g_cnt[tid] = min(run[tid], CAP);
}

// ---------------- expert GEMM: tf32 mma.sync + 4-stage cp.async pipeline ----------------
template<bool GATHER, bool RELU, int KDIM, int NDIM>
__global__ __launch_bounds__(256, 2)
void gemm_kernel(const float* __restrict__ Aglob,
                 const float* __restrict__ Wglob,
                 const float* __restrict__ biasGlob) {
    extern __shared__ char smem[];
    __shared__ int sTok[BM];

    const int e = blockIdx.z;
    const int rowBase = blockIdx.y * BM;
    const int nBase = blockIdx.x * BN;
    const int tid = threadIdx.x;

    const float* Abase = GATHER ? Aglob : (g_h + (size_t)e * CAP * KDIM);
    const float* W = Wglob + (size_t)e * KDIM * NDIM;
    const float* bias = biasGlob + e * NDIM;
    float* Out = (RELU ? g_h : g_oute) + (size_t)e * CAP * NDIM;

    if (tid < BM) {
        int r = rowBase + tid;
        sTok[tid] = GATHER ? ((r < g_cnt[e]) ? g_idx[e * CAP + r] : -1) : r;
    }
    __syncthreads();

    const unsigned smem_base = (unsigned)__cvta_generic_to_shared(smem);

    // per-thread cp.async assignments
    // A: 128 rows x 4 float4/row = 512 float4 -> 2 per thread
    const int aRow0 = tid >> 2, aC4 = (tid & 3);
    // B: 16 rows x 32 float4/row = 512 float4 -> 2 per thread
    const int bRow0 = tid >> 5, bC4 = (tid & 31);

    auto load_stage = [&](int s, int kk) {
        unsigned aBase = smem_base + s * STAGE_BYTES;
        unsigned bBase = aBase + A_STAGE_BYTES;
#pragma unroll
        for (int i = 0; i < 2; i++) {
            int row = aRow0 + i * 64;
            int tok = sTok[row];
            unsigned dst = aBase + (row * ASTR + aC4 * 4) * 4;
            const float* src = Abase + (size_t)((tok < 0) ? 0 : tok) * KDIM + kk + aC4 * 4;
            cp_async16(dst, src, (tok >= 0) ? 16 : 0);
        }
#pragma unroll
        for (int i = 0; i < 2; i++) {
            int row = bRow0 + i * 8;
            unsigned dst = bBase + (row * BSTR + bC4 * 4) * 4;
            const float* src = W + (size_t)(kk + row) * NDIM + nBase + bC4 * 4;
            cp_async16(dst, src, 16);
        }
    };

    float acc[4][4][4];
#pragma unroll
    for (int mt = 0; mt < 4; mt++)
#pragma unroll
        for (int nt = 0; nt < 4; nt++)
#pragma unroll
            for (int i = 0; i < 4; i++) acc[mt][nt][i] = 0.f;

    const int warp = tid >> 5, lane = tid & 31;
    const int wm = warp >> 2, wn = warp & 3;       // 2x4 warp grid; warp tile 64x32
    const int gid = lane >> 2, tig = lane & 3;

    const int NIT = KDIM / BK;

    // prologue: fill STAGES-1 stages
#pragma unroll
    for (int s = 0; s < STAGES - 1; s++) {
        load_stage(s, s * BK);
        cp_commit();
    }

    for (int k = 0; k < NIT; k++) {
        cp_wait2();
        __syncthreads();

        int nk = k + STAGES - 1;
        if (nk < NIT) load_stage(nk & (STAGES - 1), nk * BK);
        cp_commit();

        const int s = k & (STAGES - 1);
        const float* As = (const float*)(smem + s * STAGE_BYTES);
        const float* Bs = (const float*)(smem + s * STAGE_BYTES + A_STAGE_BYTES);

#pragma unroll
        for (int kf = 0; kf < BK; kf += 8) {
            unsigned a[4][4], b[4][2];
#pragma unroll
            for (int mt = 0; mt < 4; mt++) {
                int r = wm * 64 + mt * 16 + gid;
                a[mt][0] = __float_as_uint(to_tf32(As[r * ASTR + kf + tig]));
                a[mt][1] = __float_as_uint(to_tf32(As[(r + 8) * ASTR + kf + tig]));
                a[mt][2] = __float_as_uint(to_tf32(As[r * ASTR + kf + tig + 4]));
                a[mt][3] = __float_as_uint(to_tf32(As[(r + 8) * ASTR + kf + tig + 4]));
            }
#pragma unroll
            for (int nt = 0; nt < 4; nt++) {
                int c = wn * 32 + nt * 8 + gid;
                b[nt][0] = __float_as_uint(to_tf32(Bs[(kf + tig) * BSTR + c]));
                b[nt][1] = __float_as_uint(to_tf32(Bs[(kf + tig + 4) * BSTR + c]));
            }
#pragma unroll
            for (int mt = 0; mt < 4; mt++)
#pragma unroll
                for (int nt = 0; nt < 4; nt++)
                    mma_tf32(acc[mt][nt], a[mt], b[nt]);
        }
    }

    // epilogue: + bias (, relu), store
#pragma unroll
    for (int mt = 0; mt < 4; mt++) {
        int r0 = rowBase + wm * 64 + mt * 16 + gid;
#pragma unroll
        for (int nt = 0; nt < 4; nt++) {
            int c = nBase + wn * 32 + nt * 8 + 2 * tig;
            float bv0 = bias[c], bv1 = bias[c + 1];
            float v00 = acc[mt][nt][0] + bv0;
            float v01 = acc[mt][nt][1] + bv1;
            float v10 = acc[mt][nt][2] + bv0;
            float v11 = acc[mt][nt][3] + bv1;
            if (RELU) {
                v00 = fmaxf(v00, 0.f); v01 = fmaxf(v01, 0.f);
                v10 = fmaxf(v10, 0.f); v11 = fmaxf(v11, 0.f);
            }
            *reinterpret_cast<float2*>(Out + (size_t)r0 * NDIM + c) = make_float2(v00, v01);
            *reinterpret_cast<float2*>(Out + (size_t)(r0 + 8) * NDIM + c) = make_float2(v10, v11);
        }
    }
}

// ---------------- combine ----------------
__global__ __launch_bounds__(256) void combine_kernel(float* __restrict__ out) {
    int t = blockIdx.x;
    int i0 = g_topk_i[2 * t], i1 = g_topk_i[2 * t + 1];
    int s0 = g_slot[2 * t], s1 = g_slot[2 * t + 1];
    float w0 = g_topk_w[2 * t], w1v = g_topk_w[2 * t + 1];
    int d = threadIdx.x * 4;
    float4 a = make_float4(0.f, 0.f, 0.f, 0.f);
    if (s0 >= 0) {
        float4 v = *reinterpret_cast<const float4*>(g_oute + ((size_t)i0 * CAP + s0) * DM + d);
        a.x += w0 * v.x; a.y += w0 * v.y; a.z += w0 * v.z; a.w += w0 * v.w;
    }
    if (s1 >= 0) {
        float4 v = *reinterpret_cast<const float4*>(g_oute + ((size_t)i1 * CAP + s1) * DM + d);
        a.x += w1v * v.x; a.y += w1v * v.y; a.z += w1v * v.z; a.w += w1v * v.w;
    }
    *reinterpret_cast<float4*>(out + (size_t)t * DM + d) = a;
}

// ---------------- launch ----------------
extern "C" void kernel_launch(void* const* d_in, const int* in_sizes, int n_in,
                              void* d_out, int out_size) {
    (void)in_sizes; (void)n_in; (void)out_size;
    const float* x      = (const float*)d_in[0];
    const float* gate_w = (const float*)d_in[1];
    const float* gate_b = (const float*)d_in[2];
    const float* w1     = (const float*)d_in[3];
    const float* b1     = (const float*)d_in[4];
    const float* w2     = (const float*)d_in[5];
    const float* b2     = (const float*)d_in[6];
    float* out = (float*)d_out;

    static bool attr_done = false;
    if (!attr_done) {
        cudaFuncSetAttribute(gemm_kernel<true,  true,  DM,    FFDIM>,
                             cudaFuncAttributeMaxDynamicSharedMemorySize, SMEM_BYTES);
        cudaFuncSetAttribute(gemm_kernel<false, false, FFDIM, DM>,
                             cudaFuncAttributeMaxDynamicSharedMemorySize, SMEM_BYTES);
        attr_done = true;
    }

    gate_kernel<<<S_TOK / 8, 256>>>(x, gate_w, gate_b);
    route_kernel<<<1, 256>>>();
    gemm_kernel<true,  true,  DM,    FFDIM>
        <<<dim3(FFDIM / BN, CAP / BM, NE), 256, SMEM_BYTES>>>(x, w1, b1);
    gemm_kernel<false, false, FFDIM, DM>
        <<<dim3(DM / BN,    CAP / BM, NE), 256, SMEM_BYTES>>>(x, w2, b2);
    combine_kernel<<<S_TOK, 256>>>(out);
}